// round 3
// baseline (speedup 1.0000x reference)
#include <cuda_runtime.h>
#include <cuda_bf16.h>

#define NN 256
#define AA 1024
#define BB 64
#define CC 16
#define NW (BB * CC)   // 1024 output cols of the GEMM

// Scratch for the intermediate mat = x @ W  (1 MB) — __device__ global per alloc rules.
__device__ float g_mat[NN * NW];

// ---------------------------------------------------------------------------
// Kernel 1: fp32 SGEMM, BM=32 BN=64 BK=16, 128 threads, 4x4 register tiles.
// Grid (16, 8) = 128 blocks -> ~1 block/SM, FFMA-issue-bound by design.
// ---------------------------------------------------------------------------
__global__ __launch_bounds__(128) void md_gemm_kernel(const float* __restrict__ x,
                                                      const float* __restrict__ w) {
    __shared__ float sA[16][32];   // [k][m]  (A stored K-transposed)
    __shared__ float sB[16][64];   // [k][n]

    const int t  = threadIdx.x;
    const int bm = blockIdx.y * 32;
    const int bn = blockIdx.x * 64;
    const int ty = t >> 4;    // 0..7  -> m group (4 rows)
    const int tx = t & 15;    // 0..15 -> n group (4 cols)

    float acc[4][4] = {};

    for (int k0 = 0; k0 < AA; k0 += 16) {
        // A tile: 32x16, one float4 per thread, scatter-transpose into sA[k][m]
        {
            const int row = t >> 2;            // 0..31
            const int kc  = (t & 3) << 2;      // 0,4,8,12
            float4 v = *(const float4*)(x + (bm + row) * AA + k0 + kc);
            sA[kc + 0][row] = v.x;
            sA[kc + 1][row] = v.y;
            sA[kc + 2][row] = v.z;
            sA[kc + 3][row] = v.w;
        }
        // B tile: 16x64, two float4 per thread
        {
            const int r = t >> 4;              // 0..7
            const int c = (t & 15) << 2;       // 0..60
            *(float4*)&sB[r][c]     = *(const float4*)(w + (k0 + r) * NW + bn + c);
            *(float4*)&sB[r + 8][c] = *(const float4*)(w + (k0 + r + 8) * NW + bn + c);
        }
        __syncthreads();

        #pragma unroll
        for (int kk = 0; kk < 16; kk++) {
            float4 a = *(const float4*)&sA[kk][ty * 4];
            float4 b = *(const float4*)&sB[kk][tx * 4];
            float ar[4] = {a.x, a.y, a.z, a.w};
            float br[4] = {b.x, b.y, b.z, b.w};
            #pragma unroll
            for (int m = 0; m < 4; m++)
                #pragma unroll
                for (int n = 0; n < 4; n++)
                    acc[m][n] = fmaf(ar[m], br[n], acc[m][n]);
        }
        __syncthreads();
    }

    #pragma unroll
    for (int m = 0; m < 4; m++) {
        float4 v = make_float4(acc[m][0], acc[m][1], acc[m][2], acc[m][3]);
        *(float4*)(g_mat + (bm + ty * 4 + m) * NW + bn + tx * 4) = v;
    }
}

// ---------------------------------------------------------------------------
// Kernel 2: pairwise exp(-L1) reduction.
// Block = (b, half of j). Whole mat[:, b, :] slice (16 KB) lives in smem;
// i-loop reads are warp-uniform (broadcast). 4 partial L1 chains for ILP.
// ---------------------------------------------------------------------------
__global__ __launch_bounds__(128) void md_pairwise_kernel(const float* __restrict__ bias,
                                                          float* __restrict__ out) {
    __shared__ float sh[NN][CC];   // 256 x 16 floats = 16 KB

    const int b  = blockIdx.x;          // 0..63
    const int jt = blockIdx.y;          // 0..1
    const int t  = threadIdx.x;         // 0..127

    // Stage mat[:, b, :] into shared (float4 per thread, 8 passes)
    #pragma unroll
    for (int p = 0; p < 8; p++) {
        const int row = p * 32 + (t >> 2);
        const int c4  = (t & 3) << 2;
        *(float4*)&sh[row][c4] = *(const float4*)(g_mat + row * NW + b * CC + c4);
    }
    __syncthreads();

    const int j = jt * 128 + t;
    float my[16];
    #pragma unroll
    for (int c = 0; c < 16; c++) my[c] = sh[j][c];

    float tot0 = 0.f, tot1 = 0.f;
    #pragma unroll 2
    for (int i = 0; i < NN; i += 2) {
        // --- row i ---
        {
            const float4* r = (const float4*)sh[i];
            float4 v0 = r[0], v1 = r[1], v2 = r[2], v3 = r[3];
            float p0 = fabsf(my[0] - v0.x) + fabsf(my[1] - v0.y)
                     + fabsf(my[2] - v0.z) + fabsf(my[3] - v0.w);
            float p1 = fabsf(my[4] - v1.x) + fabsf(my[5] - v1.y)
                     + fabsf(my[6] - v1.z) + fabsf(my[7] - v1.w);
            float p2 = fabsf(my[8]  - v2.x) + fabsf(my[9]  - v2.y)
                     + fabsf(my[10] - v2.z) + fabsf(my[11] - v2.w);
            float p3 = fabsf(my[12] - v3.x) + fabsf(my[13] - v3.y)
                     + fabsf(my[14] - v3.z) + fabsf(my[15] - v3.w);
            tot0 += __expf(-((p0 + p1) + (p2 + p3)));
        }
        // --- row i+1 ---
        {
            const float4* r = (const float4*)sh[i + 1];
            float4 v0 = r[0], v1 = r[1], v2 = r[2], v3 = r[3];
            float p0 = fabsf(my[0] - v0.x) + fabsf(my[1] - v0.y)
                     + fabsf(my[2] - v0.z) + fabsf(my[3] - v0.w);
            float p1 = fabsf(my[4] - v1.x) + fabsf(my[5] - v1.y)
                     + fabsf(my[6] - v1.z) + fabsf(my[7] - v1.w);
            float p2 = fabsf(my[8]  - v2.x) + fabsf(my[9]  - v2.y)
                     + fabsf(my[10] - v2.z) + fabsf(my[11] - v2.w);
            float p3 = fabsf(my[12] - v3.x) + fabsf(my[13] - v3.y)
                     + fabsf(my[14] - v3.z) + fabsf(my[15] - v3.w);
            tot1 += __expf(-((p0 + p1) + (p2 + p3)));
        }
    }

    out[j * BB + b] = (tot0 + tot1) + bias[b];
}

// ---------------------------------------------------------------------------
// Launch. Inputs (metadata order): x [N*A] f32, weight [A*B*C] f32, bias [B] f32.
// Output: [N, B] f32.
// ---------------------------------------------------------------------------
extern "C" void kernel_launch(void* const* d_in, const int* in_sizes, int n_in,
                              void* d_out, int out_size) {
    const float* x    = (const float*)d_in[0];
    const float* w    = (const float*)d_in[1];
    const float* bias = (const float*)d_in[2];
    float* out = (float*)d_out;

    md_gemm_kernel<<<dim3(NW / 64, NN / 32), 128>>>(x, w);
    md_pairwise_kernel<<<dim3(BB, NN / 128), 128>>>(bias, out);
}

// round 4
// speedup vs baseline: 2.1075x; 2.1075x over previous
#include <cuda_runtime.h>
#include <cuda_fp16.h>
#include <cuda_bf16.h>
#include <cstdint>

#define NN 256
#define AA 1024
#define BB 64
#define CC 16
#define NW 1024   // B*C

// GEMM tiling
#define BM 32
#define BN 64
#define BK 32
#define SAS 40    // sA row stride in bf16 (32 + 8 pad) -> 80B, conflict-free
#define SBS 72    // sB row stride in bf16 (64 + 8 pad) -> 144B, conflict-free

// Intermediate mat = (x @ W) * log2(e), stored fp16. 512 KB device scratch.
__device__ __half g_math[NN * NW];

// ---------------------------------------------------------------------------
// helpers
// ---------------------------------------------------------------------------
__device__ __forceinline__ uint32_t pack_bf2(float a, float b) {
    __nv_bfloat162 h = __floats2bfloat162_rn(a, b);
    return *reinterpret_cast<uint32_t*>(&h);
}
__device__ __forceinline__ uint32_t smem_u32(const void* p) {
    return (uint32_t)__cvta_generic_to_shared(p);
}
__device__ __forceinline__ void ldsm_x4(uint32_t& r0, uint32_t& r1,
                                        uint32_t& r2, uint32_t& r3, uint32_t addr) {
    asm volatile("ldmatrix.sync.aligned.m8n8.x4.shared.b16 {%0,%1,%2,%3}, [%4];\n"
                 : "=r"(r0), "=r"(r1), "=r"(r2), "=r"(r3) : "r"(addr));
}
__device__ __forceinline__ void ldsm_x4_t(uint32_t& r0, uint32_t& r1,
                                          uint32_t& r2, uint32_t& r3, uint32_t addr) {
    asm volatile("ldmatrix.sync.aligned.m8n8.x4.trans.shared.b16 {%0,%1,%2,%3}, [%4];\n"
                 : "=r"(r0), "=r"(r1), "=r"(r2), "=r"(r3) : "r"(addr));
}
__device__ __forceinline__ void mma16816(float* c,
                                         uint32_t a0, uint32_t a1, uint32_t a2, uint32_t a3,
                                         uint32_t b0, uint32_t b1) {
    asm volatile("mma.sync.aligned.m16n8k16.row.col.f32.bf16.bf16.f32 "
                 "{%0,%1,%2,%3}, {%4,%5,%6,%7}, {%8,%9}, {%0,%1,%2,%3};\n"
                 : "+f"(c[0]), "+f"(c[1]), "+f"(c[2]), "+f"(c[3])
                 : "r"(a0), "r"(a1), "r"(a2), "r"(a3), "r"(b0), "r"(b1));
}
__device__ __forceinline__ float ex2f(float x) {
    float y; asm("ex2.approx.ftz.f32 %0, %1;" : "=f"(y) : "f"(x)); return y;
}

// ---------------------------------------------------------------------------
// Kernel 1: bf16 tensor-core GEMM, BMxBNxBK = 32x64x32, 128 thr (4 warps),
// warp tile 16x32 (4 x m16n8k16). Double-buffered smem, LDG prefetch in regs.
// Epilogue scales by log2(e) and writes fp16 to g_math.
// Grid (16 n-blocks, 8 m-blocks) = 128 blocks.
// ---------------------------------------------------------------------------
__global__ __launch_bounds__(128) void md_gemm_kernel(const float* __restrict__ x,
                                                      const float* __restrict__ w) {
    __shared__ alignas(16) __nv_bfloat16 sA[2][BM][SAS];
    __shared__ alignas(16) __nv_bfloat16 sB[2][BK][SBS];

    const int t    = threadIdx.x;
    const int lane = t & 31;
    const int wid  = t >> 5;
    const int bm   = blockIdx.y * BM;
    const int bn   = blockIdx.x * BN;
    const int wm   = (wid >> 1) * 16;   // warp m offset within block tile
    const int wn   = (wid & 1) * 32;    // warp n offset within block tile

    // gmem load assignment (fp32 -> bf16 on the way to smem)
    const int ar = t >> 2;            // 0..31 : A row / B k-row
    const int ac = (t & 3) * 8;       // A col group (8 floats)
    const int bc = (t & 3) * 16;      // B col group (16 floats)
    const float* xg = x + (bm + ar) * AA + ac;
    const float* wg = w + ar * NW + bn + bc;

    float acc[4][4] = {};
    float4 pa0, pa1, pb0, pb1, pb2, pb3;

    // ldmatrix lane addressing: row = base + (lane&15), col chunk = (lane>>4)*8
    const int lr = lane & 15;
    const int lc = (lane >> 4) * 8;

    // ---- prologue: load + store chunk 0
    pa0 = *(const float4*)(xg + 0);
    pa1 = *(const float4*)(xg + 4);
    pb0 = *(const float4*)(wg + 0);
    pb1 = *(const float4*)(wg + 4);
    pb2 = *(const float4*)(wg + 8);
    pb3 = *(const float4*)(wg + 12);
    {
        uint4 qa;
        qa.x = pack_bf2(pa0.x, pa0.y); qa.y = pack_bf2(pa0.z, pa0.w);
        qa.z = pack_bf2(pa1.x, pa1.y); qa.w = pack_bf2(pa1.z, pa1.w);
        *reinterpret_cast<uint4*>(&sA[0][ar][ac]) = qa;
        uint4 qb;
        qb.x = pack_bf2(pb0.x, pb0.y); qb.y = pack_bf2(pb0.z, pb0.w);
        qb.z = pack_bf2(pb1.x, pb1.y); qb.w = pack_bf2(pb1.z, pb1.w);
        *reinterpret_cast<uint4*>(&sB[0][ar][bc]) = qb;
        qb.x = pack_bf2(pb2.x, pb2.y); qb.y = pack_bf2(pb2.z, pb2.w);
        qb.z = pack_bf2(pb3.x, pb3.y); qb.w = pack_bf2(pb3.z, pb3.w);
        *reinterpret_cast<uint4*>(&sB[0][ar][bc + 8]) = qb;
    }
    __syncthreads();

    const int NCHUNK = AA / BK;  // 32
    for (int ck = 0; ck < NCHUNK; ck++) {
        const int buf  = ck & 1;
        const bool more = (ck + 1 < NCHUNK);
        if (more) {
            const int k0 = (ck + 1) * BK;
            pa0 = *(const float4*)(xg + k0);
            pa1 = *(const float4*)(xg + k0 + 4);
            const float* wk = wg + (size_t)k0 * NW;
            pb0 = *(const float4*)(wk + 0);
            pb1 = *(const float4*)(wk + 4);
            pb2 = *(const float4*)(wk + 8);
            pb3 = *(const float4*)(wk + 12);
        }

        // ---- compute chunk ck
        #pragma unroll
        for (int kk = 0; kk < BK; kk += 16) {
            uint32_t a0, a1, a2, a3;
            ldsm_x4(a0, a1, a2, a3, smem_u32(&sA[buf][wm + lr][kk + lc]));
            #pragma unroll
            for (int nb = 0; nb < 2; nb++) {
                uint32_t b0, b1, b2, b3;
                ldsm_x4_t(b0, b1, b2, b3,
                          smem_u32(&sB[buf][kk + lr][wn + nb * 16 + lc]));
                mma16816(acc[nb * 2 + 0], a0, a1, a2, a3, b0, b1);
                mma16816(acc[nb * 2 + 1], a0, a1, a2, a3, b2, b3);
            }
        }

        if (more) {
            const int nb_ = buf ^ 1;
            uint4 qa;
            qa.x = pack_bf2(pa0.x, pa0.y); qa.y = pack_bf2(pa0.z, pa0.w);
            qa.z = pack_bf2(pa1.x, pa1.y); qa.w = pack_bf2(pa1.z, pa1.w);
            *reinterpret_cast<uint4*>(&sA[nb_][ar][ac]) = qa;
            uint4 qb;
            qb.x = pack_bf2(pb0.x, pb0.y); qb.y = pack_bf2(pb0.z, pb0.w);
            qb.z = pack_bf2(pb1.x, pb1.y); qb.w = pack_bf2(pb1.z, pb1.w);
            *reinterpret_cast<uint4*>(&sB[nb_][ar][bc]) = qb;
            qb.x = pack_bf2(pb2.x, pb2.y); qb.y = pack_bf2(pb2.z, pb2.w);
            qb.z = pack_bf2(pb3.x, pb3.y); qb.w = pack_bf2(pb3.z, pb3.w);
            *reinterpret_cast<uint4*>(&sB[nb_][ar][bc + 8]) = qb;
        }
        __syncthreads();
    }

    // ---- epilogue: scale by log2(e), write fp16
    const float S = 1.44269504f;
    const int r0   = bm + wm + (lane >> 2);
    const int cb   = bn + wn + (lane & 3) * 2;
    #pragma unroll
    for (int nt = 0; nt < 4; nt++) {
        const int col = cb + nt * 8;
        __half2 h01 = __floats2half2_rn(acc[nt][0] * S, acc[nt][1] * S);
        __half2 h23 = __floats2half2_rn(acc[nt][2] * S, acc[nt][3] * S);
        *reinterpret_cast<__half2*>(&g_math[r0 * NW + col])       = h01;
        *reinterpret_cast<__half2*>(&g_math[(r0 + 8) * NW + col]) = h23;
    }
}

// ---------------------------------------------------------------------------
// Kernel 2: pairwise exp2(-L1') in packed fp16.
// Block = (b, j-half of 128). 256 threads: lower half i in [0,128),
// upper half i in [128,256); smem reduce. Grid (64, 2) = 128 blocks, 8 warps/SM.
// ---------------------------------------------------------------------------
__global__ __launch_bounds__(256) void md_pairwise_kernel(const float* __restrict__ bias,
                                                          float* __restrict__ out) {
    __shared__ __half sh[NN][CC];   // 8 KB, mat[:, b, :] (already * log2e)
    __shared__ float red[256];

    const int b  = blockIdx.x;
    const int jh = blockIdx.y;
    const int t  = threadIdx.x;

    // stage: thread t copies row t (32 bytes)
    {
        const uint4* src = reinterpret_cast<const uint4*>(g_math + t * NW + b * CC);
        uint4* dst = reinterpret_cast<uint4*>(sh[t]);
        dst[0] = src[0];
        dst[1] = src[1];
    }
    __syncthreads();

    const int j  = jh * 128 + (t & 127);
    const int i0 = (t >> 7) * 128;

    __half2 m[8];
    #pragma unroll
    for (int c = 0; c < 8; c++) m[c] = reinterpret_cast<const __half2*>(sh[j])[c];

    float tot0 = 0.f, tot1 = 0.f;
    #pragma unroll 4
    for (int i = i0; i < i0 + 128; i += 2) {
        {
            const __half2* v = reinterpret_cast<const __half2*>(sh[i]);
            __half2 d0 = __hsub2(m[0], v[0]), d1 = __hsub2(m[1], v[1]);
            __half2 d2 = __hsub2(m[2], v[2]), d3 = __hsub2(m[3], v[3]);
            __half2 d4 = __hsub2(m[4], v[4]), d5 = __hsub2(m[5], v[5]);
            __half2 d6 = __hsub2(m[6], v[6]), d7 = __hsub2(m[7], v[7]);
            __half2 s0 = __hadd2(__habs2(d0), __habs2(d1));
            __half2 s1 = __hadd2(__habs2(d2), __habs2(d3));
            __half2 s2 = __hadd2(__habs2(d4), __habs2(d5));
            __half2 s3 = __hadd2(__habs2(d6), __habs2(d7));
            __half2 L  = __hadd2(__hadd2(s0, s1), __hadd2(s2, s3));
            float l = __low2float(L) + __high2float(L);
            tot0 += ex2f(-l);
        }
        {
            const __half2* v = reinterpret_cast<const __half2*>(sh[i + 1]);
            __half2 d0 = __hsub2(m[0], v[0]), d1 = __hsub2(m[1], v[1]);
            __half2 d2 = __hsub2(m[2], v[2]), d3 = __hsub2(m[3], v[3]);
            __half2 d4 = __hsub2(m[4], v[4]), d5 = __hsub2(m[5], v[5]);
            __half2 d6 = __hsub2(m[6], v[6]), d7 = __hsub2(m[7], v[7]);
            __half2 s0 = __hadd2(__habs2(d0), __habs2(d1));
            __half2 s1 = __hadd2(__habs2(d2), __habs2(d3));
            __half2 s2 = __hadd2(__habs2(d4), __habs2(d5));
            __half2 s3 = __hadd2(__habs2(d6), __habs2(d7));
            __half2 L  = __hadd2(__hadd2(s0, s1), __hadd2(s2, s3));
            float l = __low2float(L) + __high2float(L);
            tot1 += ex2f(-l);
        }
    }

    red[t] = tot0 + tot1;
    __syncthreads();
    if (t < 128) {
        out[j * BB + b] = red[t] + red[t + 128] + bias[b];
    }
}

// ---------------------------------------------------------------------------
// Launch. Inputs: x [N*A] f32, weight [A*B*C] f32, bias [B] f32. Output [N,B] f32.
// ---------------------------------------------------------------------------
extern "C" void kernel_launch(void* const* d_in, const int* in_sizes, int n_in,
                              void* d_out, int out_size) {
    const float* x    = (const float*)d_in[0];
    const float* w    = (const float*)d_in[1];
    const float* bias = (const float*)d_in[2];
    float* out = (float*)d_out;

    md_gemm_kernel<<<dim3(NW / BN, NN / BM), 128>>>(x, w);
    md_pairwise_kernel<<<dim3(BB, 2), 256>>>(bias, out);
}

// round 5
// speedup vs baseline: 2.5105x; 1.1913x over previous
#include <cuda_runtime.h>
#include <cuda_fp16.h>
#include <cuda_bf16.h>
#include <cstdint>

#define NN 256
#define AA 1024
#define BB 64
#define CC 16
#define NW 1024   // B*C

// GEMM tiling
#define BM 32
#define BN 64
#define BK 32
#define KSPLIT 2
#define KHALF (AA / KSPLIT)     // 512
#define NCH   (KHALF / BK)      // 16
#define SAS 40    // sA row stride (bf16): 32 + 8 pad -> 80B (16B-multiple)
#define SBS 72    // sB row stride (bf16): 64 + 8 pad -> 144B (16B-multiple)

// Device scratch (no allocs allowed): bf16 copies of inputs + fp16 mat*log2e
__device__ __nv_bfloat16 g_xb[NN * AA];     // 512 KB
__device__ __nv_bfloat16 g_wb[AA * NW];     //   2 MB
__device__ __half        g_math[NN * NW];   // 512 KB

// ---------------------------------------------------------------------------
// helpers
// ---------------------------------------------------------------------------
__device__ __forceinline__ uint32_t pack_bf2(float a, float b) {
    __nv_bfloat162 h = __floats2bfloat162_rn(a, b);
    return *reinterpret_cast<uint32_t*>(&h);
}
__device__ __forceinline__ uint32_t smem_u32(const void* p) {
    return (uint32_t)__cvta_generic_to_shared(p);
}
__device__ __forceinline__ void cpa16(uint32_t dst, const void* src) {
    asm volatile("cp.async.cg.shared.global [%0], [%1], 16;\n" :: "r"(dst), "l"(src));
}
__device__ __forceinline__ void cpa_commit() {
    asm volatile("cp.async.commit_group;\n" ::: "memory");
}
template <int N>
__device__ __forceinline__ void cpa_wait() {
    asm volatile("cp.async.wait_group %0;\n" :: "n"(N) : "memory");
}
__device__ __forceinline__ void ldsm_x4(uint32_t& r0, uint32_t& r1,
                                        uint32_t& r2, uint32_t& r3, uint32_t addr) {
    asm volatile("ldmatrix.sync.aligned.m8n8.x4.shared.b16 {%0,%1,%2,%3}, [%4];\n"
                 : "=r"(r0), "=r"(r1), "=r"(r2), "=r"(r3) : "r"(addr));
}
__device__ __forceinline__ void ldsm_x4_t(uint32_t& r0, uint32_t& r1,
                                          uint32_t& r2, uint32_t& r3, uint32_t addr) {
    asm volatile("ldmatrix.sync.aligned.m8n8.x4.trans.shared.b16 {%0,%1,%2,%3}, [%4];\n"
                 : "=r"(r0), "=r"(r1), "=r"(r2), "=r"(r3) : "r"(addr));
}
__device__ __forceinline__ void mma16816(float* c,
                                         uint32_t a0, uint32_t a1, uint32_t a2, uint32_t a3,
                                         uint32_t b0, uint32_t b1) {
    asm volatile("mma.sync.aligned.m16n8k16.row.col.f32.bf16.bf16.f32 "
                 "{%0,%1,%2,%3}, {%4,%5,%6,%7}, {%8,%9}, {%0,%1,%2,%3};\n"
                 : "+f"(c[0]), "+f"(c[1]), "+f"(c[2]), "+f"(c[3])
                 : "r"(a0), "r"(a1), "r"(a2), "r"(a3), "r"(b0), "r"(b1));
}
__device__ __forceinline__ float ex2f(float x) {
    float y; asm("ex2.approx.ftz.f32 %0, %1;" : "=f"(y) : "f"(x)); return y;
}

// ---------------------------------------------------------------------------
// Kernel 0: fp32 -> bf16 conversion of x (blocks 0..127) and W (blocks 128..639).
// 8 elements per thread, float4 in / uint4 (8 bf16) out.
// ---------------------------------------------------------------------------
__global__ __launch_bounds__(256) void md_cvt_kernel(const float* __restrict__ x,
                                                     const float* __restrict__ w) {
    const int bid = blockIdx.x;
    const float* src;
    __nv_bfloat16* dst;
    int base;
    if (bid < 128) {                 // x: 262144 elems = 128 * 256 * 8
        base = (bid * 256 + threadIdx.x) * 8;
        src = x; dst = g_xb;
    } else {                         // w: 1048576 elems = 512 * 256 * 8
        base = ((bid - 128) * 256 + threadIdx.x) * 8;
        src = w; dst = g_wb;
    }
    float4 a = *(const float4*)(src + base);
    float4 b = *(const float4*)(src + base + 4);
    uint4 q;
    q.x = pack_bf2(a.x, a.y); q.y = pack_bf2(a.z, a.w);
    q.z = pack_bf2(b.x, b.y); q.w = pack_bf2(b.z, b.w);
    *reinterpret_cast<uint4*>(dst + base) = q;
}

// ---------------------------------------------------------------------------
// Kernel 1: bf16 tensor-core GEMM, 256 threads = 2 K-groups x 4 warps.
// Each group: 32x64 tile over K=512, BK=32 chunks, cp.async double-buffered.
// Group partials combined through smem; epilogue scales by log2(e), writes fp16.
// Grid (16, 8) = 128 blocks.
// ---------------------------------------------------------------------------
__global__ __launch_bounds__(256) void md_gemm_kernel() {
    __shared__ alignas(16) __nv_bfloat16 sA[KSPLIT][2][BM][SAS];
    __shared__ alignas(16) __nv_bfloat16 sB[KSPLIT][2][BK][SBS];
    __shared__ float red[BM][BN + 1];

    const int t    = threadIdx.x;
    const int lane = t & 31;
    const int wid  = t >> 5;
    const int g    = wid >> 2;          // K-group 0/1
    const int wl   = wid & 3;           // warp within group
    const int bm   = blockIdx.y * BM;
    const int bn   = blockIdx.x * BN;
    const int wm   = (wl >> 1) * 16;
    const int wn   = (wl & 1) * 32;
    const int tg   = t & 127;           // thread within group

    // load mapping (per group, 128 threads)
    const int arow  = tg >> 2, aseg = tg & 3;            // A: 32 rows x 4 x 16B
    const int brow0 = tg >> 3, bseg = tg & 7;            // B: 32 rows x 8 x 16B, 2 slots
    const int brow1 = brow0 + 16;
    const __nv_bfloat16* xa = g_xb + (size_t)(bm + arow) * AA + g * KHALF + aseg * 8;
    const __nv_bfloat16* wb = g_wb + (size_t)(g * KHALF) * NW + bn + bseg * 8;

    const uint32_t dA  = smem_u32(&sA[g][0][arow][aseg * 8]);
    const uint32_t dB0 = smem_u32(&sB[g][0][brow0][bseg * 8]);
    const uint32_t dB1 = smem_u32(&sB[g][0][brow1][bseg * 8]);
    const uint32_t aBuf = sizeof(__nv_bfloat16) * BM * SAS;   // buffer stride in sA
    const uint32_t bBuf = sizeof(__nv_bfloat16) * BK * SBS;   // buffer stride in sB

    auto prefetch = [&](int ck, int buf) {
        cpa16(dA  + buf * aBuf, xa + (size_t)ck * BK);
        const __nv_bfloat16* wp = wb + (size_t)ck * BK * NW;
        cpa16(dB0 + buf * bBuf, wp + (size_t)brow0 * NW);
        cpa16(dB1 + buf * bBuf, wp + (size_t)brow1 * NW);
    };

    float acc[4][4] = {};
    const int lr = lane & 15;
    const int lc = (lane >> 4) * 8;

    prefetch(0, 0);
    cpa_commit();

    for (int ck = 0; ck < NCH; ck++) {
        const int buf = ck & 1;
        if (ck + 1 < NCH) {
            prefetch(ck + 1, buf ^ 1);
            cpa_commit();
            cpa_wait<1>();
        } else {
            cpa_wait<0>();
        }
        __syncthreads();

        #pragma unroll
        for (int kk = 0; kk < BK; kk += 16) {
            uint32_t a0, a1, a2, a3;
            ldsm_x4(a0, a1, a2, a3, smem_u32(&sA[g][buf][wm + lr][kk + lc]));
            #pragma unroll
            for (int nb = 0; nb < 2; nb++) {
                uint32_t b0, b1, b2, b3;
                ldsm_x4_t(b0, b1, b2, b3,
                          smem_u32(&sB[g][buf][kk + lr][wn + nb * 16 + lc]));
                mma16816(acc[nb * 2 + 0], a0, a1, a2, a3, b0, b1);
                mma16816(acc[nb * 2 + 1], a0, a1, a2, a3, b2, b3);
            }
        }
        __syncthreads();
    }

    // combine K-group partials through smem
    const int r0 = wm + (lane >> 2);
    const int c0 = wn + (lane & 3) * 2;
    if (g == 1) {
        #pragma unroll
        for (int nt = 0; nt < 4; nt++) {
            red[r0][c0 + nt * 8]         = acc[nt][0];
            red[r0][c0 + nt * 8 + 1]     = acc[nt][1];
            red[r0 + 8][c0 + nt * 8]     = acc[nt][2];
            red[r0 + 8][c0 + nt * 8 + 1] = acc[nt][3];
        }
    }
    __syncthreads();
    if (g == 0) {
        const float S = 1.44269504f;   // log2(e): exp(-l1) == exp2(-l1*S)
        #pragma unroll
        for (int nt = 0; nt < 4; nt++) {
            float v0 = (acc[nt][0] + red[r0][c0 + nt * 8])         * S;
            float v1 = (acc[nt][1] + red[r0][c0 + nt * 8 + 1])     * S;
            float v2 = (acc[nt][2] + red[r0 + 8][c0 + nt * 8])     * S;
            float v3 = (acc[nt][3] + red[r0 + 8][c0 + nt * 8 + 1]) * S;
            const int col = bn + c0 + nt * 8;
            *reinterpret_cast<__half2*>(&g_math[(bm + r0) * NW + col])     = __floats2half2_rn(v0, v1);
            *reinterpret_cast<__half2*>(&g_math[(bm + r0 + 8) * NW + col]) = __floats2half2_rn(v2, v3);
        }
    }
}

// ---------------------------------------------------------------------------
// Kernel 2: pairwise exp2(-L1') in packed fp16.
// Block = (b, j-half). 1024 threads: j = t&127, i-range split 8 ways (t>>7).
// 8 warps/SMSP; smem tree reduce. Grid (64, 2) = 128 blocks.
// ---------------------------------------------------------------------------
__global__ __launch_bounds__(1024) void md_pairwise_kernel(const float* __restrict__ bias,
                                                           float* __restrict__ out) {
    __shared__ __half sh[NN][CC];   // 8 KB
    __shared__ float red[1024];

    const int b  = blockIdx.x;
    const int jh = blockIdx.y;
    const int t  = threadIdx.x;

    if (t < NN) {   // stage mat[:, b, :] — one 32B row per thread
        const uint4* src = reinterpret_cast<const uint4*>(g_math + t * NW + b * CC);
        uint4* dst = reinterpret_cast<uint4*>(sh[t]);
        dst[0] = src[0];
        dst[1] = src[1];
    }
    __syncthreads();

    const int j  = jh * 128 + (t & 127);
    const int i0 = (t >> 7) * 32;

    __half2 m[8];
    #pragma unroll
    for (int c = 0; c < 8; c++) m[c] = reinterpret_cast<const __half2*>(sh[j])[c];

    float tot0 = 0.f, tot1 = 0.f;
    #pragma unroll 4
    for (int i = i0; i < i0 + 32; i += 2) {
        {
            const __half2* v = reinterpret_cast<const __half2*>(sh[i]);
            __half2 d0 = __hsub2(m[0], v[0]), d1 = __hsub2(m[1], v[1]);
            __half2 d2 = __hsub2(m[2], v[2]), d3 = __hsub2(m[3], v[3]);
            __half2 d4 = __hsub2(m[4], v[4]), d5 = __hsub2(m[5], v[5]);
            __half2 d6 = __hsub2(m[6], v[6]), d7 = __hsub2(m[7], v[7]);
            __half2 s0 = __hadd2(__habs2(d0), __habs2(d1));
            __half2 s1 = __hadd2(__habs2(d2), __habs2(d3));
            __half2 s2 = __hadd2(__habs2(d4), __habs2(d5));
            __half2 s3 = __hadd2(__habs2(d6), __habs2(d7));
            __half2 L  = __hadd2(__hadd2(s0, s1), __hadd2(s2, s3));
            tot0 += ex2f(-(__low2float(L) + __high2float(L)));
        }
        {
            const __half2* v = reinterpret_cast<const __half2*>(sh[i + 1]);
            __half2 d0 = __hsub2(m[0], v[0]), d1 = __hsub2(m[1], v[1]);
            __half2 d2 = __hsub2(m[2], v[2]), d3 = __hsub2(m[3], v[3]);
            __half2 d4 = __hsub2(m[4], v[4]), d5 = __hsub2(m[5], v[5]);
            __half2 d6 = __hsub2(m[6], v[6]), d7 = __hsub2(m[7], v[7]);
            __half2 s0 = __hadd2(__habs2(d0), __habs2(d1));
            __half2 s1 = __hadd2(__habs2(d2), __habs2(d3));
            __half2 s2 = __hadd2(__habs2(d4), __habs2(d5));
            __half2 s3 = __hadd2(__habs2(d6), __habs2(d7));
            __half2 L  = __hadd2(__hadd2(s0, s1), __hadd2(s2, s3));
            tot1 += ex2f(-(__low2float(L) + __high2float(L)));
        }
    }

    red[t] = tot0 + tot1;
    __syncthreads();
    if (t < 128) {
        float s = red[t];
        #pragma unroll
        for (int q = 1; q < 8; q++) s += red[t + q * 128];
        out[j * BB + b] = s + bias[b];
    }
}

// ---------------------------------------------------------------------------
// Launch. Inputs: x [N*A] f32, weight [A*B*C] f32, bias [B] f32. Output [N,B] f32.
// ---------------------------------------------------------------------------
extern "C" void kernel_launch(void* const* d_in, const int* in_sizes, int n_in,
                              void* d_out, int out_size) {
    const float* x    = (const float*)d_in[0];
    const float* w    = (const float*)d_in[1];
    const float* bias = (const float*)d_in[2];
    float* out = (float*)d_out;

    md_cvt_kernel<<<640, 256>>>(x, w);
    md_gemm_kernel<<<dim3(NW / BN, NN / BM), 256>>>();
    md_pairwise_kernel<<<dim3(BB, 2), 1024>>>(bias, out);
}